// round 2
// baseline (speedup 1.0000x reference)
#include <cuda_runtime.h>
#include <cstdint>

// ---------------------------------------------------------------------------
// Problem constants
//   x:[32,1024,512]  w_in:[512,256]  b_in:[256]
//   kernel:[256,1024] rec_kernel:[256,1024] bias:[1024]
//   w_out:[256,256]  b_out:[256]   out:[32,1024,256] fp32
// ---------------------------------------------------------------------------
#define BB    32
#define TT    1024
#define CC    512
#define DD    256
#define UU    256
#define OO    256
#define MTOT  (BB*TT)          // 32768

// scratch (device globals: allocation-free rule)
__device__ float g_xin[(size_t)MTOT * DD];        // 33 MB
__device__ float g_xz [(size_t)MTOT * 4 * UU];    // 134 MB
__device__ float g_hs [(size_t)MTOT * UU];        // 33 MB

// ---------------------------------------------------------------------------
// Tiled fp32 GEMM:  C[M,N] = A[M,K] @ W[K,N] + bias[N]
// BM=128, BN=64, BK=16, 256 threads, 8x4 per thread. Requires
// M%128==0, N%64==0, K%16==0 (true for all three calls).
// ---------------------------------------------------------------------------
__global__ __launch_bounds__(256) void gemm_bias_kernel(
    const float* __restrict__ A, const float* __restrict__ W,
    const float* __restrict__ bias, float* __restrict__ C,
    int M, int N, int K)
{
    __shared__ float As[16][128];
    __shared__ float Bs[16][64];

    const int tid = threadIdx.x;
    const int tx  = tid & 15;      // col group (0..15) -> 4 cols
    const int ty  = tid >> 4;      // row group (0..15) -> 8 rows
    const int m0  = blockIdx.y * 128;
    const int n0  = blockIdx.x * 64;

    const int arow = tid >> 2;           // 0..63
    const int akc  = (tid & 3) * 4;      // 0,4,8,12
    const int brow = tid >> 4;           // 0..15
    const int bnc  = (tid & 15) * 4;     // 0..60

    float acc[8][4];
    #pragma unroll
    for (int i = 0; i < 8; i++)
        #pragma unroll
        for (int j = 0; j < 4; j++) acc[i][j] = 0.f;

    for (int kt = 0; kt < K; kt += 16) {
        #pragma unroll
        for (int h = 0; h < 2; h++) {
            int r = arow + h * 64;
            float4 a = *(const float4*)&A[(size_t)(m0 + r) * K + kt + akc];
            As[akc + 0][r] = a.x;
            As[akc + 1][r] = a.y;
            As[akc + 2][r] = a.z;
            As[akc + 3][r] = a.w;
        }
        {
            float4 b = *(const float4*)&W[(size_t)(kt + brow) * N + n0 + bnc];
            *(float4*)&Bs[brow][bnc] = b;
        }
        __syncthreads();

        #pragma unroll
        for (int kk = 0; kk < 16; kk++) {
            float4 b4 = *(const float4*)&Bs[kk][tx * 4];
            float4 a0 = *(const float4*)&As[kk][ty * 8];
            float4 a1 = *(const float4*)&As[kk][ty * 8 + 4];
            float a[8] = {a0.x, a0.y, a0.z, a0.w, a1.x, a1.y, a1.z, a1.w};
            #pragma unroll
            for (int i = 0; i < 8; i++) {
                acc[i][0] += a[i] * b4.x;
                acc[i][1] += a[i] * b4.y;
                acc[i][2] += a[i] * b4.z;
                acc[i][3] += a[i] * b4.w;
            }
        }
        __syncthreads();
    }

    float4 bv = *(const float4*)&bias[n0 + tx * 4];
    #pragma unroll
    for (int i = 0; i < 8; i++) {
        float4 o;
        o.x = acc[i][0] + bv.x;
        o.y = acc[i][1] + bv.y;
        o.z = acc[i][2] + bv.z;
        o.w = acc[i][3] + bv.w;
        *(float4*)&C[(size_t)(m0 + ty * 8 + i) * N + n0 + tx * 4] = o;
    }
}

// ---------------------------------------------------------------------------
// LSTM scan: 16 clusters x 8 CTAs. Cluster g owns batches {2g, 2g+1}.
// CTA rank r owns units [r*32, r*32+32); holds rec_kernel columns
// {gate*256 + r*32 + u} (128 cols x 256 rows = 128KB fp32) in SMEM.
// Per step: z[2,128] = h[2,256] @ Rslice, gates, h pushed to all 8 CTAs'
// double-buffered h via st.shared::cluster, one barrier.cluster per step.
// ---------------------------------------------------------------------------
#define CLS   8
#define UPC   32
#define LSTM_THREADS 256
#define LSTM_SMEM_FLOATS (32768 + 1024 + 2048 + 64)
#define LSTM_SMEM_BYTES  (LSTM_SMEM_FLOATS * 4)

__device__ __forceinline__ float sigm_f(float x) {
    // safe at both infinities: exp overflow -> inf -> 1/inf = 0
    return 1.f / (1.f + __expf(-x));
}
__device__ __forceinline__ float tanh_f(float x) {
    return 2.f / (1.f + __expf(-2.f * x)) - 1.f;
}

__global__ void __cluster_dims__(CLS, 1, 1) __launch_bounds__(LSTM_THREADS)
lstm_kernel(const float* __restrict__ xz, const float* __restrict__ R,
            float* __restrict__ hs)
{
    extern __shared__ float smem[];
    float* Rs    = smem;            // [256][128]  (col = gate*32 + ulocal)
    float* h2    = smem + 32768;    // [2 buf][256 k][2 batch]
    float* parts = h2 + 1024;       // [8 kc][128 col * 2 batch]
    float* cst   = parts + 2048;    // [64] cell state (b,u) = tid mapping

    const int tid  = threadIdx.x;
    const int rank = blockIdx.x;    // == ctarank (cluster spans x fully)
    const int b0   = blockIdx.y * 2;
    const int warp = tid >> 5;
    const int lane = tid & 31;

    // load R slice (one-time)
    for (int i = tid; i < 256 * 128; i += LSTM_THREADS) {
        int k = i >> 7, c = i & 127;
        int gcol = (c >> 5) * 256 + rank * UPC + (c & 31);
        Rs[i] = R[k * 1024 + gcol];
    }
    for (int i = tid; i < 512; i += LSTM_THREADS) h2[i] = 0.f;  // buf0 = h(-1)=0
    if (tid < 64) cst[tid] = 0.f;
    __syncthreads();
    asm volatile("barrier.cluster.arrive.aligned;\n" ::: "memory");
    asm volatile("barrier.cluster.wait.aligned;\n" ::: "memory");

    const int bb = tid & 1;         // gate-thread batch (tid<64)
    const int u  = tid >> 1;        // gate-thread local unit
    const int kg = rank * UPC + u;  // global unit index

    const float4* R4 = (const float4*)Rs;

    for (int t = 0; t < TT; t++) {
        const int rb = t & 1, wb = rb ^ 1;

        // prefetch xz for gate threads (consumed ~1300 cyc later)
        float xzv0 = 0.f, xzv1 = 0.f, xzv2 = 0.f, xzv3 = 0.f;
        if (tid < 64) {
            size_t base = ((size_t)(b0 + bb) * TT + t) * 1024 + rank * UPC + u;
            xzv0 = xz[base];
            xzv1 = xz[base + 256];
            xzv2 = xz[base + 512];
            xzv3 = xz[base + 768];
        }

        // z = h @ Rslice ; warp = k-chunk, lane = 4-col group
        float a00 = 0.f, a01 = 0.f, a10 = 0.f, a11 = 0.f;
        float a20 = 0.f, a21 = 0.f, a30 = 0.f, a31 = 0.f;
        const float2* hb = (const float2*)(h2 + rb * 512);
        #pragma unroll 8
        for (int j = 0; j < 32; j++) {
            int k = warp * 32 + j;
            float2 hh = hb[k];                    // broadcast
            float4 r4 = R4[k * 32 + lane];        // conflict-free
            a00 += r4.x * hh.x;  a01 += r4.x * hh.y;
            a10 += r4.y * hh.x;  a11 += r4.y * hh.y;
            a20 += r4.z * hh.x;  a21 += r4.z * hh.y;
            a30 += r4.w * hh.x;  a31 += r4.w * hh.y;
        }
        float4* pp = (float4*)(parts + warp * 256 + lane * 8);
        pp[0] = make_float4(a00, a01, a10, a11);
        pp[1] = make_float4(a20, a21, a30, a31);
        __syncthreads();

        if (tid < 64) {
            float z0 = xzv0, z1 = xzv1, z2 = xzv2, z3 = xzv3;
            #pragma unroll
            for (int kc = 0; kc < 8; kc++) {
                const float* p = parts + kc * 256 + bb;
                z0 += p[(0 * 32 + u) * 2];
                z1 += p[(1 * 32 + u) * 2];
                z2 += p[(2 * 32 + u) * 2];
                z3 += p[(3 * 32 + u) * 2];
            }
            float ig = sigm_f(z0);
            float fg = sigm_f(z1);
            float gg = tanh_f(z2);
            float og = sigm_f(z3);
            float c  = fg * cst[tid] + ig * gg;
            cst[tid] = c;
            float h  = og * tanh_f(c);

            hs[((size_t)(b0 + bb) * TT + t) * UU + kg] = h;

            // push h slice into every CTA's write-buffer
            unsigned laddr =
                (unsigned)__cvta_generic_to_shared(&h2[wb * 512 + kg * 2 + bb]);
            #pragma unroll
            for (int pr = 0; pr < CLS; pr++) {
                unsigned ra;
                asm volatile("mapa.shared::cluster.u32 %0, %1, %2;"
                             : "=r"(ra) : "r"(laddr), "r"(pr));
                asm volatile("st.shared::cluster.f32 [%0], %1;"
                             :: "r"(ra), "f"(h) : "memory");
            }
        }
        // release/acquire: DSMEM h writes visible cluster-wide after wait
        asm volatile("barrier.cluster.arrive.aligned;\n" ::: "memory");
        asm volatile("barrier.cluster.wait.aligned;\n" ::: "memory");
    }
}

// ---------------------------------------------------------------------------
// launch
// ---------------------------------------------------------------------------
extern "C" void kernel_launch(void* const* d_in, const int* in_sizes, int n_in,
                              void* d_out, int out_size)
{
    const float* x      = (const float*)d_in[0];
    const float* w_in   = (const float*)d_in[1];
    const float* b_in   = (const float*)d_in[2];
    const float* kernel = (const float*)d_in[3];
    const float* rec_k  = (const float*)d_in[4];
    const float* bias   = (const float*)d_in[5];
    const float* w_out  = (const float*)d_in[6];
    const float* b_out  = (const float*)d_in[7];
    float* out = (float*)d_out;

    float *p_xin, *p_xz, *p_hs;
    cudaGetSymbolAddress((void**)&p_xin, g_xin);
    cudaGetSymbolAddress((void**)&p_xz,  g_xz);
    cudaGetSymbolAddress((void**)&p_hs,  g_hs);

    cudaFuncSetAttribute(lstm_kernel,
                         cudaFuncAttributeMaxDynamicSharedMemorySize,
                         LSTM_SMEM_BYTES);

    // 1) xin = x @ w_in + b_in          [32768,512]x[512,256]
    gemm_bias_kernel<<<dim3(DD / 64, MTOT / 128), 256>>>(
        x, w_in, b_in, p_xin, MTOT, DD, CC);

    // 2) xz = xin @ kernel + bias       [32768,256]x[256,1024]
    gemm_bias_kernel<<<dim3((4 * UU) / 64, MTOT / 128), 256>>>(
        p_xin, kernel, bias, p_xz, MTOT, 4 * UU, DD);

    // 3) LSTM scan over T=1024
    lstm_kernel<<<dim3(CLS, BB / 2), LSTM_THREADS, LSTM_SMEM_BYTES>>>(
        p_xz, rec_k, p_hs);

    // 4) out = hs @ w_out + b_out       [32768,256]x[256,256]
    gemm_bias_kernel<<<dim3(OO / 64, MTOT / 128), 256>>>(
        p_hs, w_out, b_out, out, MTOT, OO, UU);
}

// round 3
// speedup vs baseline: 1.0945x; 1.0945x over previous
#include <cuda_runtime.h>
#include <cstdint>

// ---------------------------------------------------------------------------
// Problem constants
//   x:[32,1024,512]  w_in:[512,256]  b_in:[256]
//   kernel:[256,1024] rec_kernel:[256,1024] bias:[1024]
//   w_out:[256,256]  b_out:[256]   out:[32,1024,256] fp32
// ---------------------------------------------------------------------------
#define BB    32
#define TT    1024
#define CC    512
#define DD    256
#define UU    256
#define OO    256
#define MTOT  (BB*TT)          // 32768

// scratch (device globals: allocation-free rule)
__device__ float g_xin[(size_t)MTOT * DD];        // 33 MB
__device__ float g_xz [(size_t)MTOT * 4 * UU];    // 134 MB
__device__ float g_hs [(size_t)MTOT * UU];        // 33 MB

// ---------------------------------------------------------------------------
// Tiled fp32 GEMM:  C[M,N] = A[M,K] @ W[K,N] + bias[N]   (unchanged from R2)
// ---------------------------------------------------------------------------
__global__ __launch_bounds__(256) void gemm_bias_kernel(
    const float* __restrict__ A, const float* __restrict__ W,
    const float* __restrict__ bias, float* __restrict__ C,
    int M, int N, int K)
{
    __shared__ float As[16][128];
    __shared__ float Bs[16][64];

    const int tid = threadIdx.x;
    const int tx  = tid & 15;
    const int ty  = tid >> 4;
    const int m0  = blockIdx.y * 128;
    const int n0  = blockIdx.x * 64;

    const int arow = tid >> 2;
    const int akc  = (tid & 3) * 4;
    const int brow = tid >> 4;
    const int bnc  = (tid & 15) * 4;

    float acc[8][4];
    #pragma unroll
    for (int i = 0; i < 8; i++)
        #pragma unroll
        for (int j = 0; j < 4; j++) acc[i][j] = 0.f;

    for (int kt = 0; kt < K; kt += 16) {
        #pragma unroll
        for (int h = 0; h < 2; h++) {
            int r = arow + h * 64;
            float4 a = *(const float4*)&A[(size_t)(m0 + r) * K + kt + akc];
            As[akc + 0][r] = a.x;
            As[akc + 1][r] = a.y;
            As[akc + 2][r] = a.z;
            As[akc + 3][r] = a.w;
        }
        {
            float4 b = *(const float4*)&W[(size_t)(kt + brow) * N + n0 + bnc];
            *(float4*)&Bs[brow][bnc] = b;
        }
        __syncthreads();

        #pragma unroll
        for (int kk = 0; kk < 16; kk++) {
            float4 b4 = *(const float4*)&Bs[kk][tx * 4];
            float4 a0 = *(const float4*)&As[kk][ty * 8];
            float4 a1 = *(const float4*)&As[kk][ty * 8 + 4];
            float a[8] = {a0.x, a0.y, a0.z, a0.w, a1.x, a1.y, a1.z, a1.w};
            #pragma unroll
            for (int i = 0; i < 8; i++) {
                acc[i][0] += a[i] * b4.x;
                acc[i][1] += a[i] * b4.y;
                acc[i][2] += a[i] * b4.z;
                acc[i][3] += a[i] * b4.w;
            }
        }
        __syncthreads();
    }

    float4 bv = *(const float4*)&bias[n0 + tx * 4];
    #pragma unroll
    for (int i = 0; i < 8; i++) {
        float4 o;
        o.x = acc[i][0] + bv.x;
        o.y = acc[i][1] + bv.y;
        o.z = acc[i][2] + bv.z;
        o.w = acc[i][3] + bv.w;
        *(float4*)&C[(size_t)(m0 + ty * 8 + i) * N + n0 + tx * 4] = o;
    }
}

// ---------------------------------------------------------------------------
// LSTM scan v2:
//   16 clusters x 8 CTAs, cluster g owns batches {2g,2g+1}.
//   CTA rank r owns 128 gate-columns {gate*256 + r*32 + u}.
//   R slice lives in REGISTERS: thread (w=tid/32, l=tid%32) holds
//   R[k=32w..32w+32) x cols (4l..4l+3) as 64 packed f32x2 pairs (128 regs).
//   MMA via fma.rn.f32x2 (2 fp32 MACs/instr): FMA floor 1024 -> ~512 cyc.
//   Cross-CTA h exchange: st.async.shared::cluster + mbarrier complete_tx
//   (2 barriers, one per h buffer) -- no barrier.cluster in the loop.
// ---------------------------------------------------------------------------
#define CLS 8
#define LSTM_THREADS 256

__device__ __forceinline__ float sigm_f(float x) {
    return 1.f / (1.f + __expf(-x));
}
__device__ __forceinline__ float tanh_f(float x) {
    return 2.f / (1.f + __expf(-2.f * x)) - 1.f;
}

#define FMA2(acc, a, b) \
    asm("fma.rn.f32x2 %0, %1, %2, %0;" : "+l"(acc) : "l"(a), "l"(b))

#define MBAR_INIT(addr, cnt) \
    asm volatile("mbarrier.init.shared.b64 [%0], %1;" :: "r"(addr), "r"(cnt) : "memory")

#define MBAR_EXPECT_TX(addr, tx) \
    asm volatile("mbarrier.arrive.expect_tx.shared.b64 _, [%0], %1;" :: "r"(addr), "r"(tx) : "memory")

#define MBAR_WAIT_CLUSTER(addr, par) do {                                          \
    asm volatile("{\n\t.reg .pred P;\n"                                            \
                 "W_%=:\n\t"                                                       \
                 "mbarrier.try_wait.parity.acquire.cluster.shared::cta.b64 "       \
                 "P, [%0], %1, 0x989680;\n\t"                                      \
                 "@!P bra W_%=;\n\t}"                                              \
                 :: "r"(addr), "r"(par) : "memory");                               \
} while (0)

__global__ void __cluster_dims__(CLS, 1, 1) __launch_bounds__(LSTM_THREADS)
lstm_kernel(const float* __restrict__ xz, const float* __restrict__ R,
            float* __restrict__ hs)
{
    __shared__ float h2[2 * 512];        // [buf][k=256][b=2]
    __shared__ float parts[16 * 128];    // [w=8][b=2][c=128]
    __shared__ __align__(8) unsigned long long mbar[2];

    const int tid  = threadIdx.x;
    const int rank = blockIdx.x;
    const int b0   = blockIdx.y * 2;
    const int w    = tid >> 5;
    const int l    = tid & 31;

    // ---- load R slice into registers (one-time) ----
    // thread owns cols 4l..4l+3 (all same gate group), k = 32w..32w+32
    const int gate = l >> 3;
    const int cb   = (4 * l) & 31;
    const int gcol = gate * 256 + rank * 32 + cb;
    ulonglong2 Rreg[32];                 // [j].x = (c0,c1), [j].y = (c2,c3)
    #pragma unroll
    for (int j = 0; j < 32; j++)
        Rreg[j] = *(const ulonglong2*)&R[(size_t)(w * 32 + j) * 1024 + gcol];

    for (int i = tid; i < 1024; i += LSTM_THREADS) h2[i] = 0.f;

    const unsigned mb0 = (unsigned)__cvta_generic_to_shared(&mbar[0]);
    if (tid == 0) {
        MBAR_INIT(mb0, 1);
        MBAR_INIT(mb0 + 8, 1);
        MBAR_EXPECT_TX(mb0, 2048);       // arm for t=0 pushes
        MBAR_EXPECT_TX(mb0 + 8, 2048);   // arm for t=1 pushes
        asm volatile("fence.mbarrier_init.release.cluster;" ::: "memory");
    }
    __syncthreads();
    asm volatile("barrier.cluster.arrive.aligned;" ::: "memory");
    asm volatile("barrier.cluster.wait.aligned;"   ::: "memory");

    // gate-thread (tid<64) identity
    const int gb = tid >> 5;             // batch
    const int gu = tid & 31;             // local unit
    float creg = 0.f;                    // cell state in register

    for (int t = 0; t < TT; t++) {
        const int rb = t & 1, wb = rb ^ 1;

        // xz prefetch (independent of the wait)
        float xzv0 = 0.f, xzv1 = 0.f, xzv2 = 0.f, xzv3 = 0.f;
        if (tid < 64) {
            size_t base = ((size_t)(b0 + gb) * TT + t) * 1024 + rank * 32 + gu;
            xzv0 = xz[base];
            xzv1 = xz[base + 256];
            xzv2 = xz[base + 512];
            xzv3 = xz[base + 768];
        }

        if (t > 0) {
            const unsigned wm = mb0 + (unsigned)(((t - 1) & 1) * 8);
            MBAR_WAIT_CLUSTER(wm, ((t - 1) >> 1) & 1);
            if (tid == 0) MBAR_EXPECT_TX(wm, 2048);   // re-arm for t+1 pushes
        }

        // ---- MMA: z_partial[cols 4l..4l+3][b0..b1] over k in [32w,32w+32) ----
        unsigned long long a00 = 0ull, a01 = 0ull, a10 = 0ull, a11 = 0ull;
        const float2* hb = (const float2*)(h2 + rb * 512);
        #pragma unroll
        for (int j = 0; j < 32; j++) {
            float2 hh = hb[w * 32 + j];                 // LDS.64 broadcast
            unsigned hx = __float_as_uint(hh.x);
            unsigned hy = __float_as_uint(hh.y);
            unsigned long long hp0, hp1;
            asm("mov.b64 %0, {%1, %1};" : "=l"(hp0) : "r"(hx));
            asm("mov.b64 %0, {%1, %1};" : "=l"(hp1) : "r"(hy));
            FMA2(a00, Rreg[j].x, hp0);                  // (c0,c1) batch0
            FMA2(a01, Rreg[j].x, hp1);                  // (c0,c1) batch1
            FMA2(a10, Rreg[j].y, hp0);                  // (c2,c3) batch0
            FMA2(a11, Rreg[j].y, hp1);                  // (c2,c3) batch1
        }
        {
            unsigned p0, p1, p2, p3;
            asm("mov.b64 {%0, %1}, %2;" : "=r"(p0), "=r"(p1) : "l"(a00));
            asm("mov.b64 {%0, %1}, %2;" : "=r"(p2), "=r"(p3) : "l"(a10));
            *(float4*)&parts[(w * 2 + 0) * 128 + 4 * l] =
                make_float4(__uint_as_float(p0), __uint_as_float(p1),
                            __uint_as_float(p2), __uint_as_float(p3));
            asm("mov.b64 {%0, %1}, %2;" : "=r"(p0), "=r"(p1) : "l"(a01));
            asm("mov.b64 {%0, %1}, %2;" : "=r"(p2), "=r"(p3) : "l"(a11));
            *(float4*)&parts[(w * 2 + 1) * 128 + 4 * l] =
                make_float4(__uint_as_float(p0), __uint_as_float(p1),
                            __uint_as_float(p2), __uint_as_float(p3));
        }
        __syncthreads();

        // ---- gates + push (64 threads) ----
        if (tid < 64) {
            float z0 = xzv0, z1 = xzv1, z2 = xzv2, z3 = xzv3;
            #pragma unroll
            for (int ww = 0; ww < 8; ww++) {
                const float* p = &parts[(ww * 2 + gb) * 128];
                z0 += p[gu];
                z1 += p[32 + gu];
                z2 += p[64 + gu];
                z3 += p[96 + gu];
            }
            float ig = sigm_f(z0);
            float fg = sigm_f(z1);
            float gg = tanh_f(z2);
            float og = sigm_f(z3);
            creg = fg * creg + ig * gg;
            float h = og * tanh_f(creg);

            hs[((size_t)(b0 + gb) * TT + t) * UU + rank * 32 + gu] = h;

            if (t < TT - 1) {
                const unsigned dl = (unsigned)__cvta_generic_to_shared(
                    &h2[wb * 512 + (rank * 32 + gu) * 2 + gb]);
                const unsigned ml = mb0 + (unsigned)((t & 1) * 8);
                const unsigned hv = __float_as_uint(h);
                #pragma unroll
                for (int pr = 0; pr < CLS; pr++) {
                    unsigned rd, rm;
                    asm volatile("mapa.shared::cluster.u32 %0, %1, %2;"
                                 : "=r"(rd) : "r"(dl), "r"(pr));
                    asm volatile("mapa.shared::cluster.u32 %0, %1, %2;"
                                 : "=r"(rm) : "r"(ml), "r"(pr));
                    asm volatile(
                        "st.async.shared::cluster.mbarrier::complete_tx::bytes.b32 "
                        "[%0], %1, [%2];"
                        :: "r"(rd), "r"(hv), "r"(rm) : "memory");
                }
            }
        }
        // no per-step cluster barrier: mbarrier tx-count is the sync
    }

    // drain before exit (cheap, once)
    asm volatile("barrier.cluster.arrive.aligned;" ::: "memory");
    asm volatile("barrier.cluster.wait.aligned;"   ::: "memory");
}

// ---------------------------------------------------------------------------
// launch
// ---------------------------------------------------------------------------
extern "C" void kernel_launch(void* const* d_in, const int* in_sizes, int n_in,
                              void* d_out, int out_size)
{
    const float* x      = (const float*)d_in[0];
    const float* w_in   = (const float*)d_in[1];
    const float* b_in   = (const float*)d_in[2];
    const float* kernel = (const float*)d_in[3];
    const float* rec_k  = (const float*)d_in[4];
    const float* bias   = (const float*)d_in[5];
    const float* w_out  = (const float*)d_in[6];
    const float* b_out  = (const float*)d_in[7];
    float* out = (float*)d_out;

    float *p_xin, *p_xz, *p_hs;
    cudaGetSymbolAddress((void**)&p_xin, g_xin);
    cudaGetSymbolAddress((void**)&p_xz,  g_xz);
    cudaGetSymbolAddress((void**)&p_hs,  g_hs);

    // 1) xin = x @ w_in + b_in          [32768,512]x[512,256]
    gemm_bias_kernel<<<dim3(DD / 64, MTOT / 128), 256>>>(
        x, w_in, b_in, p_xin, MTOT, DD, CC);

    // 2) xz = xin @ kernel + bias       [32768,256]x[256,1024]
    gemm_bias_kernel<<<dim3((4 * UU) / 64, MTOT / 128), 256>>>(
        p_xin, kernel, bias, p_xz, MTOT, 4 * UU, DD);

    // 3) LSTM scan over T=1024
    lstm_kernel<<<dim3(CLS, BB / 2), LSTM_THREADS>>>(p_xz, rec_k, p_hs);

    // 4) out = hs @ w_out + b_out       [32768,256]x[256,256]
    gemm_bias_kernel<<<dim3(OO / 64, MTOT / 128), 256>>>(
        p_hs, w_out, b_out, out, MTOT, OO, UU);
}

// round 4
// speedup vs baseline: 1.1956x; 1.0924x over previous
#include <cuda_runtime.h>
#include <cstdint>

// ---------------------------------------------------------------------------
// Problem constants
//   x:[32,1024,512]  w_in:[512,256]  b_in:[256]
//   kernel:[256,1024] rec_kernel:[256,1024] bias:[1024]
//   w_out:[256,256]  b_out:[256]   out:[32,1024,256] fp32
// ---------------------------------------------------------------------------
#define BB    32
#define TT    1024
#define CC    512
#define DD    256
#define UU    256
#define OO    256
#define MTOT  (BB*TT)          // 32768

__device__ float g_xin[(size_t)MTOT * DD];
__device__ float g_xz [(size_t)MTOT * 4 * UU];
__device__ float g_hs [(size_t)MTOT * UU];

// ---------------------------------------------------------------------------
// Tiled fp32 GEMM (unchanged): C[M,N] = A[M,K] @ W[K,N] + bias[N]
// ---------------------------------------------------------------------------
__global__ __launch_bounds__(256) void gemm_bias_kernel(
    const float* __restrict__ A, const float* __restrict__ W,
    const float* __restrict__ bias, float* __restrict__ C,
    int M, int N, int K)
{
    __shared__ float As[16][128];
    __shared__ float Bs[16][64];

    const int tid = threadIdx.x;
    const int tx  = tid & 15;
    const int ty  = tid >> 4;
    const int m0  = blockIdx.y * 128;
    const int n0  = blockIdx.x * 64;

    const int arow = tid >> 2;
    const int akc  = (tid & 3) * 4;
    const int brow = tid >> 4;
    const int bnc  = (tid & 15) * 4;

    float acc[8][4];
    #pragma unroll
    for (int i = 0; i < 8; i++)
        #pragma unroll
        for (int j = 0; j < 4; j++) acc[i][j] = 0.f;

    for (int kt = 0; kt < K; kt += 16) {
        #pragma unroll
        for (int h = 0; h < 2; h++) {
            int r = arow + h * 64;
            float4 a = *(const float4*)&A[(size_t)(m0 + r) * K + kt + akc];
            As[akc + 0][r] = a.x;
            As[akc + 1][r] = a.y;
            As[akc + 2][r] = a.z;
            As[akc + 3][r] = a.w;
        }
        {
            float4 b = *(const float4*)&W[(size_t)(kt + brow) * N + n0 + bnc];
            *(float4*)&Bs[brow][bnc] = b;
        }
        __syncthreads();

        #pragma unroll
        for (int kk = 0; kk < 16; kk++) {
            float4 b4 = *(const float4*)&Bs[kk][tx * 4];
            float4 a0 = *(const float4*)&As[kk][ty * 8];
            float4 a1 = *(const float4*)&As[kk][ty * 8 + 4];
            float a[8] = {a0.x, a0.y, a0.z, a0.w, a1.x, a1.y, a1.z, a1.w};
            #pragma unroll
            for (int i = 0; i < 8; i++) {
                acc[i][0] += a[i] * b4.x;
                acc[i][1] += a[i] * b4.y;
                acc[i][2] += a[i] * b4.z;
                acc[i][3] += a[i] * b4.w;
            }
        }
        __syncthreads();
    }

    float4 bv = *(const float4*)&bias[n0 + tx * 4];
    #pragma unroll
    for (int i = 0; i < 8; i++) {
        float4 o;
        o.x = acc[i][0] + bv.x;
        o.y = acc[i][1] + bv.y;
        o.z = acc[i][2] + bv.z;
        o.w = acc[i][3] + bv.w;
        *(float4*)&C[(size_t)(m0 + ty * 8 + i) * N + n0 + tx * 4] = o;
    }
}

// ---------------------------------------------------------------------------
// LSTM scan v3:
//   16 clusters x 8 CTAs; cluster owns 2 batches; CTA rank r owns 128 gate
//   columns {gate*256 + r*32 + u}; R slice register-resident (f32x2 MMA).
//   h exchange: staged in SMEM, ONE cp.async.bulk (256B) per peer per step.
//   Per-source mbarriers: warp w waits ONLY on rank w's 256B slice.
//   Warps 2..7 bar.arrive and run ahead; gate warps (0,1) reduce+push.
// ---------------------------------------------------------------------------
#define CLS 8
#define LSTM_THREADS 256

__device__ __forceinline__ float sigm_f(float x) {
    return 1.f / (1.f + __expf(-x));
}
__device__ __forceinline__ float tanh_f(float x) {
    return 2.f / (1.f + __expf(-2.f * x)) - 1.f;
}

#define FMA2(acc, a, b) \
    asm("fma.rn.f32x2 %0, %1, %2, %0;" : "+l"(acc) : "l"(a), "l"(b))

#define MBAR_INIT(addr, cnt) \
    asm volatile("mbarrier.init.shared.b64 [%0], %1;" :: "r"(addr), "r"(cnt) : "memory")

#define MBAR_EXPECT_TX(addr, tx) \
    asm volatile("mbarrier.arrive.expect_tx.shared.b64 _, [%0], %1;" :: "r"(addr), "r"(tx) : "memory")

#define MBAR_WAIT(addr, par) do {                                                  \
    asm volatile("{\n\t.reg .pred P;\n"                                            \
                 "W_%=:\n\t"                                                       \
                 "mbarrier.try_wait.parity.acquire.cluster.shared::cta.b64 "       \
                 "P, [%0], %1, 0x989680;\n\t"                                      \
                 "@!P bra W_%=;\n\t}"                                              \
                 :: "r"(addr), "r"(par) : "memory");                               \
} while (0)

__global__ void __cluster_dims__(CLS, 1, 1) __launch_bounds__(LSTM_THREADS)
lstm_kernel(const float* __restrict__ xz, const float* __restrict__ R,
            float* __restrict__ hs)
{
    __shared__ __align__(16) float h2[2 * 512];         // [buf][k=256][b=2]
    __shared__ __align__(16) float parts[2][16 * 128];  // [buf][w*2+b][c=128]
    __shared__ __align__(16) float hstage[64];          // [u=32][b=2] staged h
    __shared__ __align__(8)  unsigned long long mbar[16]; // [buf][src=8]

    const int tid  = threadIdx.x;
    const int rank = blockIdx.x;
    const int b0   = blockIdx.y * 2;
    const int w    = tid >> 5;
    const int l    = tid & 31;

    // ---- R slice -> registers: thread (w,l) holds k=32w..32w+32, cols 4l..4l+3
    const int gate = l >> 3;
    const int cb   = (4 * l) & 31;
    const int gcol = gate * 256 + rank * 32 + cb;
    ulonglong2 Rreg[32];
    #pragma unroll
    for (int j = 0; j < 32; j++)
        Rreg[j] = *(const ulonglong2*)&R[(size_t)(w * 32 + j) * 1024 + gcol];

    for (int i = tid; i < 1024; i += LSTM_THREADS) h2[i] = 0.f;

    const unsigned mb0 = (unsigned)__cvta_generic_to_shared(&mbar[0]);
    if (tid == 0) {
        #pragma unroll
        for (int i = 0; i < 16; i++) {
            MBAR_INIT(mb0 + i * 8, 1);
            MBAR_EXPECT_TX(mb0 + i * 8, 256);   // pre-arm both buffers
        }
        asm volatile("fence.mbarrier_init.release.cluster;" ::: "memory");
    }
    __syncthreads();
    asm volatile("barrier.cluster.arrive.aligned;" ::: "memory");
    asm volatile("barrier.cluster.wait.aligned;"   ::: "memory");

    const int gb = tid >> 5;            // gate-thread batch  (tid<64)
    const int gu = tid & 31;            // gate-thread unit
    float creg = 0.f;
    int ph0 = 0, ph1 = 0;               // per-warp parity for the 2 buffers

    const unsigned dst_l[2] = {
        (unsigned)__cvta_generic_to_shared(&h2[0 * 512 + rank * 64]),
        (unsigned)__cvta_generic_to_shared(&h2[1 * 512 + rank * 64])};
    const unsigned src_l =
        (unsigned)__cvta_generic_to_shared(&hstage[0]);

    for (int t = 0; t < TT; t++) {
        const int pb = t & 1;

        // xz prefetch (gate threads only) — issued before any wait
        float xzv0 = 0.f, xzv1 = 0.f, xzv2 = 0.f, xzv3 = 0.f;
        if (tid < 64) {
            size_t base = ((size_t)(b0 + gb) * TT + t) * 1024 + rank * 32 + gu;
            xzv0 = xz[base];
            xzv1 = xz[base + 256];
            xzv2 = xz[base + 512];
            xzv3 = xz[base + 768];
        }

        // wait ONLY for our source slice (rank w -> units 32w..32w+32)
        if (t > 0) {
            const unsigned m = mb0 + (unsigned)((pb * 8 + w) * 8);
            if (pb) { MBAR_WAIT(m, ph1); ph1 ^= 1; }
            else    { MBAR_WAIT(m, ph0); ph0 ^= 1; }
            if (l == 0) MBAR_EXPECT_TX(m, 256);   // re-arm for t+2
        }

        // ---- MMA: z_partial over k in [32w,32w+32), cols 4l..4l+3, b=0,1
        unsigned long long a00 = 0ull, a01 = 0ull, a10 = 0ull, a11 = 0ull;
        const float2* hb = (const float2*)(h2 + pb * 512) + w * 32;
        #pragma unroll
        for (int j = 0; j < 32; j++) {
            float2 hh = hb[j];
            unsigned hx = __float_as_uint(hh.x);
            unsigned hy = __float_as_uint(hh.y);
            unsigned long long hp0, hp1;
            asm("mov.b64 %0, {%1, %1};" : "=l"(hp0) : "r"(hx));
            asm("mov.b64 %0, {%1, %1};" : "=l"(hp1) : "r"(hy));
            FMA2(a00, Rreg[j].x, hp0);
            FMA2(a01, Rreg[j].x, hp1);
            FMA2(a10, Rreg[j].y, hp0);
            FMA2(a11, Rreg[j].y, hp1);
        }
        {
            float* pbuf = parts[pb];
            unsigned p0, p1, p2, p3;
            asm("mov.b64 {%0, %1}, %2;" : "=r"(p0), "=r"(p1) : "l"(a00));
            asm("mov.b64 {%0, %1}, %2;" : "=r"(p2), "=r"(p3) : "l"(a10));
            *(float4*)&pbuf[(w * 2 + 0) * 128 + 4 * l] =
                make_float4(__uint_as_float(p0), __uint_as_float(p1),
                            __uint_as_float(p2), __uint_as_float(p3));
            asm("mov.b64 {%0, %1}, %2;" : "=r"(p0), "=r"(p1) : "l"(a01));
            asm("mov.b64 {%0, %1}, %2;" : "=r"(p2), "=r"(p3) : "l"(a11));
            *(float4*)&pbuf[(w * 2 + 1) * 128 + 4 * l] =
                make_float4(__uint_as_float(p0), __uint_as_float(p1),
                            __uint_as_float(p2), __uint_as_float(p3));
        }

        if (w >= 2) {
            // publish partials, run ahead into next step's wait+MMA
            asm volatile("bar.arrive 2, 256;" ::: "memory");
            continue;
        }
        asm volatile("bar.sync 2, 256;" ::: "memory");

        // ---- gate phase (warps 0,1 == the 64 gate threads) ----
        {
            const float* pbuf = parts[pb];
            float z0 = xzv0, z1 = xzv1, z2 = xzv2, z3 = xzv3;
            #pragma unroll
            for (int ww = 0; ww < 8; ww++) {
                const float* p = &pbuf[(ww * 2 + gb) * 128];
                z0 += p[gu];
                z1 += p[32 + gu];
                z2 += p[64 + gu];
                z3 += p[96 + gu];
            }
            float ig = sigm_f(z0);
            float fg = sigm_f(z1);
            float gg = tanh_f(z2);
            float og = sigm_f(z3);
            creg = fg * creg + ig * gg;
            float h = og * tanh_f(creg);

            hs[((size_t)(b0 + gb) * TT + t) * UU + rank * 32 + gu] = h;

            if (t < TT - 1) {
                hstage[gu * 2 + gb] = h;
                asm volatile("bar.sync 1, 64;" ::: "memory");
                asm volatile("fence.proxy.async.shared::cta;" ::: "memory");
                if (tid == 0) {
                    const int nb = pb ^ 1;
                    const unsigned dl = dst_l[nb];
                    const unsigned ml = mb0 + (unsigned)((nb * 8 + rank) * 8);
                    #pragma unroll
                    for (int pr = 0; pr < CLS; pr++) {
                        unsigned rd, rm;
                        asm volatile("mapa.shared::cluster.u32 %0, %1, %2;"
                                     : "=r"(rd) : "r"(dl), "r"(pr));
                        asm volatile("mapa.shared::cluster.u32 %0, %1, %2;"
                                     : "=r"(rm) : "r"(ml), "r"(pr));
                        asm volatile(
                            "cp.async.bulk.shared::cluster.shared::cta"
                            ".mbarrier::complete_tx::bytes [%0], [%1], 256, [%2];"
                            :: "r"(rd), "r"(src_l), "r"(rm) : "memory");
                    }
                }
            }
        }
    }

    asm volatile("barrier.cluster.arrive.aligned;" ::: "memory");
    asm volatile("barrier.cluster.wait.aligned;"   ::: "memory");
}

// ---------------------------------------------------------------------------
// launch
// ---------------------------------------------------------------------------
extern "C" void kernel_launch(void* const* d_in, const int* in_sizes, int n_in,
                              void* d_out, int out_size)
{
    const float* x      = (const float*)d_in[0];
    const float* w_in   = (const float*)d_in[1];
    const float* b_in   = (const float*)d_in[2];
    const float* kernel = (const float*)d_in[3];
    const float* rec_k  = (const float*)d_in[4];
    const float* bias   = (const float*)d_in[5];
    const float* w_out  = (const float*)d_in[6];
    const float* b_out  = (const float*)d_in[7];
    float* out = (float*)d_out;

    float *p_xin, *p_xz, *p_hs;
    cudaGetSymbolAddress((void**)&p_xin, g_xin);
    cudaGetSymbolAddress((void**)&p_xz,  g_xz);
    cudaGetSymbolAddress((void**)&p_hs,  g_hs);

    // 1) xin = x @ w_in + b_in          [32768,512]x[512,256]
    gemm_bias_kernel<<<dim3(DD / 64, MTOT / 128), 256>>>(
        x, w_in, b_in, p_xin, MTOT, DD, CC);

    // 2) xz = xin @ kernel + bias       [32768,256]x[256,1024]
    gemm_bias_kernel<<<dim3((4 * UU) / 64, MTOT / 128), 256>>>(
        p_xin, kernel, bias, p_xz, MTOT, 4 * UU, DD);

    // 3) LSTM scan over T=1024
    lstm_kernel<<<dim3(CLS, BB / 2), LSTM_THREADS>>>(p_xz, rec_k, p_hs);

    // 4) out = hs @ w_out + b_out       [32768,256]x[256,256]
    gemm_bias_kernel<<<dim3(OO / 64, MTOT / 128), 256>>>(
        p_hs, w_out, b_out, out, MTOT, OO, UU);
}

// round 5
// speedup vs baseline: 1.3613x; 1.1385x over previous
#include <cuda_runtime.h>
#include <cstdint>

// ---------------------------------------------------------------------------
// Problem constants
//   x:[32,1024,512]  w_in:[512,256]  b_in:[256]
//   kernel:[256,1024] rec_kernel:[256,1024] bias:[1024]
//   w_out:[256,256]  b_out:[256]   out:[32,1024,256] fp32
// ---------------------------------------------------------------------------
#define BB    32
#define TT    1024
#define CC    512
#define DD    256
#define UU    256
#define OO    256
#define MTOT  (BB*TT)          // 32768

__device__ float g_xin[(size_t)MTOT * DD];
__device__ float g_xz [(size_t)MTOT * 4 * UU];
__device__ float g_hs [(size_t)MTOT * UU];

// tiny no-op kernels: shift launch index so ncu (-s 5 -c 1) captures the LSTM
__global__ void noop_kernel(int* p) { if (p) *p = 0; }

// ---------------------------------------------------------------------------
// Tiled fp32 GEMM (unchanged): C[M,N] = A[M,K] @ W[K,N] + bias[N]
// ---------------------------------------------------------------------------
__global__ __launch_bounds__(256) void gemm_bias_kernel(
    const float* __restrict__ A, const float* __restrict__ W,
    const float* __restrict__ bias, float* __restrict__ C,
    int M, int N, int K)
{
    __shared__ float As[16][128];
    __shared__ float Bs[16][64];

    const int tid = threadIdx.x;
    const int tx  = tid & 15;
    const int ty  = tid >> 4;
    const int m0  = blockIdx.y * 128;
    const int n0  = blockIdx.x * 64;

    const int arow = tid >> 2;
    const int akc  = (tid & 3) * 4;
    const int brow = tid >> 4;
    const int bnc  = (tid & 15) * 4;

    float acc[8][4];
    #pragma unroll
    for (int i = 0; i < 8; i++)
        #pragma unroll
        for (int j = 0; j < 4; j++) acc[i][j] = 0.f;

    for (int kt = 0; kt < K; kt += 16) {
        #pragma unroll
        for (int h = 0; h < 2; h++) {
            int r = arow + h * 64;
            float4 a = *(const float4*)&A[(size_t)(m0 + r) * K + kt + akc];
            As[akc + 0][r] = a.x;
            As[akc + 1][r] = a.y;
            As[akc + 2][r] = a.z;
            As[akc + 3][r] = a.w;
        }
        {
            float4 b = *(const float4*)&W[(size_t)(kt + brow) * N + n0 + bnc];
            *(float4*)&Bs[brow][bnc] = b;
        }
        __syncthreads();

        #pragma unroll
        for (int kk = 0; kk < 16; kk++) {
            float4 b4 = *(const float4*)&Bs[kk][tx * 4];
            float4 a0 = *(const float4*)&As[kk][ty * 8];
            float4 a1 = *(const float4*)&As[kk][ty * 8 + 4];
            float a[8] = {a0.x, a0.y, a0.z, a0.w, a1.x, a1.y, a1.z, a1.w};
            #pragma unroll
            for (int i = 0; i < 8; i++) {
                acc[i][0] += a[i] * b4.x;
                acc[i][1] += a[i] * b4.y;
                acc[i][2] += a[i] * b4.z;
                acc[i][3] += a[i] * b4.w;
            }
        }
        __syncthreads();
    }

    float4 bv = *(const float4*)&bias[n0 + tx * 4];
    #pragma unroll
    for (int i = 0; i < 8; i++) {
        float4 o;
        o.x = acc[i][0] + bv.x;
        o.y = acc[i][1] + bv.y;
        o.z = acc[i][2] + bv.z;
        o.w = acc[i][3] + bv.w;
        *(float4*)&C[(size_t)(m0 + ty * 8 + i) * N + n0 + tx * 4] = o;
    }
}

// ---------------------------------------------------------------------------
// LSTM scan v4: v3 + tight try_wait hint, parallel peer pushes, STG off the
// critical path. Structure otherwise identical to v3 (proved correct).
// ---------------------------------------------------------------------------
#define CLS 8
#define LSTM_THREADS 256

__device__ __forceinline__ float sigm_f(float x) {
    return 1.f / (1.f + __expf(-x));
}
__device__ __forceinline__ float tanh_f(float x) {
    return 2.f / (1.f + __expf(-2.f * x)) - 1.f;
}

#define FMA2(acc, a, b) \
    asm("fma.rn.f32x2 %0, %1, %2, %0;" : "+l"(acc) : "l"(a), "l"(b))

#define MBAR_INIT(addr, cnt) \
    asm volatile("mbarrier.init.shared.b64 [%0], %1;" :: "r"(addr), "r"(cnt) : "memory")

#define MBAR_EXPECT_TX(addr, tx) \
    asm volatile("mbarrier.arrive.expect_tx.shared.b64 _, [%0], %1;" :: "r"(addr), "r"(tx) : "memory")

// tight wait: small suspend hint (128ns) instead of 10ms
#define MBAR_WAIT(addr, par) do {                                                  \
    asm volatile("{\n\t.reg .pred P;\n"                                            \
                 "W_%=:\n\t"                                                       \
                 "mbarrier.try_wait.parity.acquire.cluster.shared::cta.b64 "       \
                 "P, [%0], %1, 0x80;\n\t"                                          \
                 "@!P bra W_%=;\n\t}"                                              \
                 :: "r"(addr), "r"(par) : "memory");                               \
} while (0)

__global__ void __cluster_dims__(CLS, 1, 1) __launch_bounds__(LSTM_THREADS, 1)
lstm_kernel(const float* __restrict__ xz, const float* __restrict__ R,
            float* __restrict__ hs)
{
    __shared__ __align__(16) float h2[2 * 512];         // [buf][k=256][b=2]
    __shared__ __align__(16) float parts[2][16 * 128];  // [buf][w*2+b][c=128]
    __shared__ __align__(16) float hstage[64];          // [u=32][b=2]
    __shared__ __align__(8)  unsigned long long mbar[16]; // [buf][src=8]

    const int tid  = threadIdx.x;
    const int rank = blockIdx.x;
    const int b0   = blockIdx.y * 2;
    const int w    = tid >> 5;
    const int l    = tid & 31;

    // ---- R slice -> registers: thread (w,l) holds k=32w..32w+32, cols 4l..4l+3
    const int gate = l >> 3;
    const int cb   = (4 * l) & 31;
    const int gcol = gate * 256 + rank * 32 + cb;
    ulonglong2 Rreg[32];
    #pragma unroll
    for (int j = 0; j < 32; j++)
        Rreg[j] = *(const ulonglong2*)&R[(size_t)(w * 32 + j) * 1024 + gcol];

    for (int i = tid; i < 1024; i += LSTM_THREADS) h2[i] = 0.f;

    const unsigned mb0 = (unsigned)__cvta_generic_to_shared(&mbar[0]);
    if (tid == 0) {
        #pragma unroll
        for (int i = 0; i < 16; i++) {
            MBAR_INIT(mb0 + i * 8, 1);
            MBAR_EXPECT_TX(mb0 + i * 8, 256);
        }
        asm volatile("fence.mbarrier_init.release.cluster;" ::: "memory");
    }
    __syncthreads();
    asm volatile("barrier.cluster.arrive.aligned;" ::: "memory");
    asm volatile("barrier.cluster.wait.aligned;"   ::: "memory");

    const int gb = tid >> 5;            // gate-thread batch  (tid<64)
    const int gu = tid & 31;            // gate-thread unit
    float creg = 0.f;
    int ph0 = 0, ph1 = 0;

    const unsigned dst_l[2] = {
        (unsigned)__cvta_generic_to_shared(&h2[0 * 512 + rank * 64]),
        (unsigned)__cvta_generic_to_shared(&h2[1 * 512 + rank * 64])};
    const unsigned src_l =
        (unsigned)__cvta_generic_to_shared(&hstage[0]);

    for (int t = 0; t < TT; t++) {
        const int pb = t & 1;

        // xz prefetch (gate threads only), issued before any wait
        float xzv0 = 0.f, xzv1 = 0.f, xzv2 = 0.f, xzv3 = 0.f;
        if (tid < 64) {
            size_t base = ((size_t)(b0 + gb) * TT + t) * 1024 + rank * 32 + gu;
            xzv0 = xz[base];
            xzv1 = xz[base + 256];
            xzv2 = xz[base + 512];
            xzv3 = xz[base + 768];
        }

        // wait ONLY for our source slice (rank w -> units 32w..32w+32)
        if (t > 0) {
            const unsigned m = mb0 + (unsigned)((pb * 8 + w) * 8);
            if (pb) { MBAR_WAIT(m, ph1); ph1 ^= 1; }
            else    { MBAR_WAIT(m, ph0); ph0 ^= 1; }
            if (l == 0) MBAR_EXPECT_TX(m, 256);   // re-arm for t+2
        }

        // ---- MMA: z_partial over k in [32w,32w+32), cols 4l..4l+3, b=0,1
        unsigned long long a00 = 0ull, a01 = 0ull, a10 = 0ull, a11 = 0ull;
        const float2* hb = (const float2*)(h2 + pb * 512) + w * 32;
        #pragma unroll
        for (int j = 0; j < 32; j++) {
            float2 hh = hb[j];
            unsigned hx = __float_as_uint(hh.x);
            unsigned hy = __float_as_uint(hh.y);
            unsigned long long hp0, hp1;
            asm("mov.b64 %0, {%1, %1};" : "=l"(hp0) : "r"(hx));
            asm("mov.b64 %0, {%1, %1};" : "=l"(hp1) : "r"(hy));
            FMA2(a00, Rreg[j].x, hp0);
            FMA2(a01, Rreg[j].x, hp1);
            FMA2(a10, Rreg[j].y, hp0);
            FMA2(a11, Rreg[j].y, hp1);
        }
        {
            float* pbuf = parts[pb];
            unsigned p0, p1, p2, p3;
            asm("mov.b64 {%0, %1}, %2;" : "=r"(p0), "=r"(p1) : "l"(a00));
            asm("mov.b64 {%0, %1}, %2;" : "=r"(p2), "=r"(p3) : "l"(a10));
            *(float4*)&pbuf[(w * 2 + 0) * 128 + 4 * l] =
                make_float4(__uint_as_float(p0), __uint_as_float(p1),
                            __uint_as_float(p2), __uint_as_float(p3));
            asm("mov.b64 {%0, %1}, %2;" : "=r"(p0), "=r"(p1) : "l"(a01));
            asm("mov.b64 {%0, %1}, %2;" : "=r"(p2), "=r"(p3) : "l"(a11));
            *(float4*)&pbuf[(w * 2 + 1) * 128 + 4 * l] =
                make_float4(__uint_as_float(p0), __uint_as_float(p1),
                            __uint_as_float(p2), __uint_as_float(p3));
        }

        if (w >= 2) {
            asm volatile("bar.arrive 2, 256;" ::: "memory");
            continue;                      // run ahead into next step
        }
        asm volatile("bar.sync 2, 256;" ::: "memory");

        // ---- gate phase (warps 0,1 == 64 gate threads) ----
        {
            const float* pbuf = parts[pb];
            float z0 = xzv0, z1 = xzv1, z2 = xzv2, z3 = xzv3;
            #pragma unroll
            for (int ww = 0; ww < 8; ww++) {
                const float* p = &pbuf[(ww * 2 + gb) * 128];
                z0 += p[gu];
                z1 += p[32 + gu];
                z2 += p[64 + gu];
                z3 += p[96 + gu];
            }
            float ig = sigm_f(z0);
            float fg = sigm_f(z1);
            float gg = tanh_f(z2);
            float og = sigm_f(z3);
            creg = fg * creg + ig * gg;
            float h = og * tanh_f(creg);

            if (t < TT - 1) {
                hstage[gu * 2 + gb] = h;
                asm volatile("bar.sync 1, 64;" ::: "memory");
                if (tid < 8) {
                    // threads 0..7 push to peers 0..7 in parallel
                    asm volatile("fence.proxy.async.shared::cta;" ::: "memory");
                    const int nb = pb ^ 1;
                    const unsigned dl = dst_l[nb];
                    const unsigned ml = mb0 + (unsigned)((nb * 8 + rank) * 8);
                    unsigned rd, rm;
                    asm volatile("mapa.shared::cluster.u32 %0, %1, %2;"
                                 : "=r"(rd) : "r"(dl), "r"(tid));
                    asm volatile("mapa.shared::cluster.u32 %0, %1, %2;"
                                 : "=r"(rm) : "r"(ml), "r"(tid));
                    asm volatile(
                        "cp.async.bulk.shared::cluster.shared::cta"
                        ".mbarrier::complete_tx::bytes [%0], [%1], 256, [%2];"
                        :: "r"(rd), "r"(src_l), "r"(rm) : "memory");
                }
            }
            // global store off the critical path
            hs[((size_t)(b0 + gb) * TT + t) * UU + rank * 32 + gu] = h;
        }
    }

    asm volatile("barrier.cluster.arrive.aligned;" ::: "memory");
    asm volatile("barrier.cluster.wait.aligned;"   ::: "memory");
}

// ---------------------------------------------------------------------------
// launch
// ---------------------------------------------------------------------------
extern "C" void kernel_launch(void* const* d_in, const int* in_sizes, int n_in,
                              void* d_out, int out_size)
{
    const float* x      = (const float*)d_in[0];
    const float* w_in   = (const float*)d_in[1];
    const float* b_in   = (const float*)d_in[2];
    const float* kernel = (const float*)d_in[3];
    const float* rec_k  = (const float*)d_in[4];
    const float* bias   = (const float*)d_in[5];
    const float* w_out  = (const float*)d_in[6];
    const float* b_out  = (const float*)d_in[7];
    float* out = (float*)d_out;

    float *p_xin, *p_xz, *p_hs;
    cudaGetSymbolAddress((void**)&p_xin, g_xin);
    cudaGetSymbolAddress((void**)&p_xz,  g_xz);
    cudaGetSymbolAddress((void**)&p_hs,  g_hs);

    // 3 no-op launches: makes the LSTM the 6th launch so ncu -s 5 captures it
    noop_kernel<<<1, 32>>>(nullptr);
    noop_kernel<<<1, 32>>>(nullptr);
    noop_kernel<<<1, 32>>>(nullptr);

    // 1) xin = x @ w_in + b_in          [32768,512]x[512,256]
    gemm_bias_kernel<<<dim3(DD / 64, MTOT / 128), 256>>>(
        x, w_in, b_in, p_xin, MTOT, DD, CC);

    // 2) xz = xin @ kernel + bias       [32768,256]x[256,1024]
    gemm_bias_kernel<<<dim3((4 * UU) / 64, MTOT / 128), 256>>>(
        p_xin, kernel, bias, p_xz, MTOT, 4 * UU, DD);

    // 3) LSTM scan over T=1024
    lstm_kernel<<<dim3(CLS, BB / 2), LSTM_THREADS>>>(p_xz, rec_k, p_hs);

    // 4) out = hs @ w_out + b_out       [32768,256]x[256,256]
    gemm_bias_kernel<<<dim3(OO / 64, MTOT / 128), 256>>>(
        p_hs, w_out, b_out, out, MTOT, OO, UU);
}